// round 16
// baseline (speedup 1.0000x reference)
#include <cuda_runtime.h>
#include <cuda_bf16.h>
#include <math.h>

#define BMAX 2048
#define KD   256
#define PD   256
#define SD   10
#define SP   5              // sample pairs
#define SROWS 4             // k-rows per pipeline stage (per warp)
#define NIT2 32             // stages per k-half (128/4)
#define WSTG 512            // floats per warp-stage (4 rows x 128 cols)
#define NSLOT 3             // ring slots per warp
#define WREG (NSLOT * WSTG) // 1536 floats per warp pool region
#define NTHR 128            // threads: warp = (k-half, col-half); thread = 4 cols

// per-batch partial results + completion counter (allocation-free scratch)
__device__ float g_pen[BMAX];
__device__ float g_lmse[BMAX];
__device__ unsigned int g_ctr = 0;

typedef unsigned long long u64;

__device__ __forceinline__ u64 ffma2(u64 a, u64 b, u64 c) {
    u64 d;
    asm("fma.rn.f32x2 %0, %1, %2, %3;" : "=l"(d) : "l"(a), "l"(b), "l"(c));
    return d;
}
__device__ __forceinline__ u64 bcast2(float p) {
    u64 d; unsigned u = __float_as_uint(p);
    asm("mov.b64 %0, {%1, %1};" : "=l"(d) : "r"(u));
    return d;
}
__device__ __forceinline__ float2 unpack2(u64 a) {
    float2 r;
    asm("mov.b64 {%0, %1}, %2;" : "=f"(r.x), "=f"(r.y) : "l"(a));
    return r;
}
__device__ __forceinline__ void cpa16(unsigned saddr, const float* g) {
    asm volatile("cp.async.cg.shared.global [%0], [%1], 16;" :: "r"(saddr), "l"(g));
}
__device__ __forceinline__ void cpa_commit() {
    asm volatile("cp.async.commit_group;");
}

__global__ __launch_bounds__(NTHR, 6)
void vil_main_kernel(const float* __restrict__ y_pred,
                     const float* __restrict__ y_true,
                     const float* __restrict__ Pp,
                     const float* __restrict__ params,
                     const float* __restrict__ Xs,
                     float* __restrict__ out, int out_size, int Bn)
{
    const int b    = blockIdx.x;
    const int tid  = threadIdx.x;
    const int lane = tid & 31;
    const int w    = tid >> 5;

    __shared__ float2 xsp[SP][KD];                   // masked X, 10 KB
    __shared__ __align__(16) float pool[4 * WREG];   // 24 KB: per-warp 3-slot rings; later cacc+merge
    __shared__ float hms[SD];
    __shared__ unsigned int lastflag;

    float (*cacc)[PD] = (float (*)[PD])pool;         // [SD][PD] alias (post-GEMM)

    const int n  = (int)params[b * 3 + 0];
    const int kb = (int)params[b * 3 + 1];
    const int mb = (int)params[b * 3 + 2];
    const int nk = n - kb;

    // warp roles: ks = k-half (0/1), ch = col-half (0/1)
    const int ks    = w >> 1;
    const int ch    = w & 1;
    const int k0w   = ks * 128;
    const int cbase = ch * 128;              // warp's 128-column window
    // thread's 4 columns: cbase + 4*lane .. +3

    // DEAD-COLUMN SKIP: columns j >= nk are masked to -1 downstream and never
    // contribute — don't load them. Garbage (stale smem) flows only into
    // dead-column accumulators, which the selection mask discards.
    const bool ldp = (cbase + 4 * lane) < nk;

    const float* Pbase  = Pp + (size_t)b * KD * PD;
    const float* PbaseW = Pbase + (size_t)k0w * PD + cbase + lane * 4;  // row r of stage s: + (s*4+r)*PD
    float*       wreg   = pool + w * WREG;
    const unsigned wreg_sh = (unsigned)__cvta_generic_to_shared(pool) + (w * WREG + lane * 4) * 4;

    // ---- prologue: issue this warp's quarter of stages 0..1 (live cols only) ----
#pragma unroll
    for (int it = 0; it < 2; it++) {
        unsigned dst = wreg_sh + it * WSTG * 4;
        const float* src = PbaseW + it * SROWS * PD;
        if (ldp) {
#pragma unroll
            for (int r = 0; r < SROWS; r++) cpa16(dst + r * 128 * 4, src + r * PD);
        }
        cpa_commit();
    }

    // ---- load X[b], masked, packed as (x[2sp][k], x[2sp+1][k]) ----
    const float* Xb = Xs + (size_t)b * SD * KD;
    for (int idx = tid; idx < SP * KD; idx += NTHR) {
        int s = idx >> 8;
        int k = idx & (KD - 1);
        float a = Xb[(2 * s)     * KD + k];
        float c = Xb[(2 * s + 1) * KD + k];
        if (k >= kb) { a = 0.0f; c = 0.0f; }
        xsp[s][k] = make_float2(a, c);
    }
    __syncthreads();   // publish X

    // acc[sp][c]: sample-pair sp, column cbase+4*lane+c
    u64 acc[SP][4];
#pragma unroll
    for (int s = 0; s < SP; s++)
#pragma unroll
        for (int c = 0; c < 4; c++) acc[s][c] = 0ull;

    // ---- barrier-free pipelined GEMM mainloop (warp-private quarter, 3-slot ring) ----
    int slot  = 0;   // slot of stage `it`
    int slot2 = 2;   // slot receiving stage `it+2` (== slot of it-1, consumed last iter)
    for (int it = 0; it < NIT2; it++) {
        // issue FIRST: stage it+2 into the slot this warp consumed last iteration
        if (it + 2 < NIT2) {
            unsigned dst = wreg_sh + slot2 * WSTG * 4;
            const float* src = PbaseW + (it + 2) * SROWS * PD;
            if (ldp) {
#pragma unroll
                for (int r = 0; r < SROWS; r++) cpa16(dst + r * 128 * 4, src + r * PD);
            }
            cpa_commit();
        }
        // wait: stage `it` resident (pending groups allowed: 2/1/0)
        if (it <= NIT2 - 3)      asm volatile("cp.async.wait_group 2;");
        else if (it == NIT2 - 2) asm volatile("cp.async.wait_group 1;");
        else                     asm volatile("cp.async.wait_group 0;");

        const float* st = wreg + slot * WSTG;
        const int kk = k0w + it * SROWS;
#pragma unroll
        for (int u = 0; u < SROWS; u += 2) {
            float4 p0 = *(const float4*)&st[u * 128 + lane * 4];        // P[kk+u][4 cols]
            float4 p1 = *(const float4*)&st[(u + 1) * 128 + lane * 4];  // P[kk+u+1][4 cols]
            u64 a0 = bcast2(p0.x), a1 = bcast2(p0.y), a2 = bcast2(p0.z), a3 = bcast2(p0.w);
            u64 b0 = bcast2(p1.x), b1 = bcast2(p1.y), b2 = bcast2(p1.z), b3 = bcast2(p1.w);
#pragma unroll
            for (int s = 0; s < SP; s++) {
                // one LDS.128: x sample-pairs for kk+u, kk+u+1 (broadcast) -> feeds 8 FFMA2
                const ulonglong2 xq = *(const ulonglong2*)&xsp[s][kk + u];
                acc[s][0] = ffma2(xq.x, a0, acc[s][0]);
                acc[s][1] = ffma2(xq.x, a1, acc[s][1]);
                acc[s][2] = ffma2(xq.x, a2, acc[s][2]);
                acc[s][3] = ffma2(xq.x, a3, acc[s][3]);
                acc[s][0] = ffma2(xq.y, b0, acc[s][0]);
                acc[s][1] = ffma2(xq.y, b1, acc[s][1]);
                acc[s][2] = ffma2(xq.y, b2, acc[s][2]);
                acc[s][3] = ffma2(xq.y, b3, acc[s][3]);
            }
        }
        slot  = (slot  == NSLOT - 1) ? 0 : slot  + 1;
        slot2 = (slot2 == NSLOT - 1) ? 0 : slot2 + 1;
    }

    // ---- k-half merge: ks=1 warps stash partials in their OWN pool regions,
    //      ks=0 warps add. (Own groups drained by wait_group 0; sync below
    //      orders all cross-warp reads/writes.) ----
    if (ks == 1) {
        u64* mbuf = (u64*)(pool + w * WREG);   // 20 u64/lane = 1280 floats < WREG=1536
#pragma unroll
        for (int s = 0; s < SP; s++)
#pragma unroll
            for (int c = 0; c < 4; c++) mbuf[lane * 20 + s * 4 + c] = acc[s][c];
    }
    __syncthreads();
    if (ks == 0) {
        const u64* mbuf = (const u64*)(pool + (w + 2) * WREG);   // partner warp's stash
#pragma unroll
        for (int s = 0; s < SP; s++) {
            float2 v[4];
#pragma unroll
            for (int c = 0; c < 4; c++) {
                float2 mine = unpack2(acc[s][c]);
                float2 oth  = unpack2(mbuf[lane * 20 + s * 4 + c]);
                v[c] = make_float2(mine.x + oth.x, mine.y + oth.y);
            }
            // cacc rows 2s, 2s+1 at this thread's 4 columns (cacc spans [0,2560) —
            // disjoint from ks=1 stash regions at [3072,3712) and [4608,5248))
            *(float4*)&cacc[2 * s][cbase + 4 * lane]     = make_float4(v[0].x, v[1].x, v[2].x, v[3].x);
            *(float4*)&cacc[2 * s + 1][cbase + 4 * lane] = make_float4(v[0].y, v[1].y, v[2].y, v[3].y);
        }
    }
    __syncthreads();

    // ---- per-sample top-(m+1) via iterative max extraction (1 warp / sample) ----
    for (int s = w; s < SD; s += 4) {
        float v[16];
#pragma unroll
        for (int i = 0; i < 8; i++) {
            int idx = lane + 32 * i;
            float2 xv = xsp[s >> 1][idx];
            float x = (s & 1) ? xv.y : xv.x;
            v[i] = (idx < kb) ? fabsf(x) : -1.0f;
        }
#pragma unroll
        for (int i = 0; i < 8; i++) {
            int j = lane + 32 * i;
            v[8 + i] = (j < nk) ? fabsf(cacc[s][j]) : -1.0f;
        }

        float cmax = 0.0f, cm = 0.0f;
        for (int pass = 0;; pass++) {
            float lm = v[0];
#pragma unroll
            for (int i = 1; i < 16; i++) lm = fmaxf(lm, v[i]);
            float wm = lm;
#pragma unroll
            for (int off = 16; off; off >>= 1)
                wm = fmaxf(wm, __shfl_xor_sync(0xffffffffu, wm, off));
            if (pass == 0)  cmax = wm;
            if (pass == mb) { cm = wm; break; }
            // remove exactly ONE instance of wm (matches sort semantics on ties)
            unsigned bal = __ballot_sync(0xffffffffu, lm == wm);
            int src = __ffs(bal) - 1;
            if (lane == src) {
                bool done = false;
#pragma unroll
                for (int i = 0; i < 16; i++) {
                    if (!done && v[i] == wm) { v[i] = -3.0e38f; done = true; }
                }
            }
        }
        if (lane == 0) hms[s] = cmax / (cm + 1e-9f);
    }
    __syncthreads();

    // ---- per-batch terms + last-CTA-done grid reduction ----
    if (tid == 0) {
        float mh = hms[0];
#pragma unroll
        for (int s = 1; s < SD; s++) mh = fmaxf(mh, hms[s]);
        float yp = y_pred[b];
        float pen = ((mb + 1) <= n) ? fmaxf(mh - yp, 0.0f) : 0.0f;
        g_pen[b] = pen;
        float lp = log2f(fmaxf(yp, 1e-9f));
        float lt = log2f(fmaxf(y_true[b], 1e-9f));
        float d  = lt - lp;
        g_lmse[b] = d * d;
        __threadfence();
        unsigned int old = atomicAdd(&g_ctr, 1u);
        lastflag = (old == (unsigned)(Bn - 1)) ? 1u : 0u;
    }
    __syncthreads();

    if (lastflag) {
        __threadfence();   // acquire: observe all CTAs' g_pen/g_lmse writes
        __shared__ float sp[NTHR], sl[NTHR];
        float p = 0.0f, l = 0.0f;
        for (int i = tid; i < Bn; i += NTHR) { p += g_pen[i]; l += g_lmse[i]; }
        sp[tid] = p; sl[tid] = l;
        __syncthreads();
        for (int o = NTHR / 2; o; o >>= 1) {
            if (tid < o) { sp[tid] += sp[tid + o]; sl[tid] += sl[tid + o]; }
            __syncthreads();
        }
        if (tid == 0) {
            float lmse = sl[0] / (float)Bn;
            float viol = sp[0] / (float)Bn;
            float tot  = lmse + 0.5f * viol;
            if (out_size > 0) out[0] = tot;
            if (out_size > 1) out[1] = lmse;
            if (out_size > 2) out[2] = viol;
            g_ctr = 0;   // reset for next graph replay
        }
    }
}

extern "C" void kernel_launch(void* const* d_in, const int* in_sizes, int n_in,
                              void* d_out, int out_size)
{
    const float* y_pred = (const float*)d_in[0];
    const float* y_true = (const float*)d_in[1];
    const float* Pp     = (const float*)d_in[2];
    const float* params = (const float*)d_in[3];
    const float* Xs     = (const float*)d_in[4];
    float* out = (float*)d_out;

    int Bn = in_sizes[0];
    if (Bn > BMAX) Bn = BMAX;

    vil_main_kernel<<<Bn, NTHR>>>(y_pred, y_true, Pp, params, Xs, out, out_size, Bn);
}